// round 7
// baseline (speedup 1.0000x reference)
#include <cuda_runtime.h>
#include <cstdint>

// ---------------- problem constants ----------------
#define BB 4
#define CC 256
#define HH 96
#define WW 320
#define HW (HH * WW)          // 30720
#define MT 64                 // queries per CTA
#define KC 16                 // K per chunk (one mma k-step)
#define NCHUNK (CC / KC)      // 16
#define NTH 512               // 16 warps: 2(M) x 8(N)
#define RAD 4
#define NCH 36
#define VOL_STRIDE 322

// ---------------- smem layout (bytes) ----------------
#define BSTR 656              // B row stride: 328 halves (41*16B, conflict-free)
#define ASTR 176              // A row stride: 88 halves (11*16B)
#define OFF_BH 0
#define OFF_BL (KC * BSTR)            // 10496
#define OFF_AH (2 * KC * BSTR)        // 20992
#define OFF_AL (OFF_AH + KC * ASTR)   // 23808
#define STAGE_BYTES (OFF_AL + KC * ASTR)       // 26624 (x2 = 53248)
#define VOL_BYTES (MT * VOL_STRIDE * 4)        // 82432
#define SMEM_BYTES (VOL_BYTES)                 // vol overlays both stages

static __device__ __forceinline__ uint32_t smem_u32(const void* p) {
    uint32_t a;
    asm("{ .reg .u64 t; cvta.to.shared.u64 t, %1; cvt.u32.u64 %0, t; }" : "=r"(a) : "l"(p));
    return a;
}

static __device__ __forceinline__ void ldsm4t(uint32_t* r, uint32_t a) {
    asm volatile("ldmatrix.sync.aligned.m8n8.x4.trans.shared.b16 {%0,%1,%2,%3}, [%4];"
                 : "=r"(r[0]), "=r"(r[1]), "=r"(r[2]), "=r"(r[3]) : "r"(a));
}
static __device__ __forceinline__ void ldsm2t(uint32_t* r, uint32_t a) {
    asm volatile("ldmatrix.sync.aligned.m8n8.x2.trans.shared.b16 {%0,%1}, [%2];"
                 : "=r"(r[0]), "=r"(r[1]) : "r"(a));
}
static __device__ __forceinline__ void mma16816(float* d, const uint32_t* a, const uint32_t* b) {
    asm volatile("mma.sync.aligned.m16n8k16.row.col.f32.bf16.bf16.f32 "
                 "{%0,%1,%2,%3}, {%4,%5,%6,%7}, {%8,%9}, {%0,%1,%2,%3};"
                 : "+f"(d[0]), "+f"(d[1]), "+f"(d[2]), "+f"(d[3])
                 : "r"(a[0]), "r"(a[1]), "r"(a[2]), "r"(a[3]), "r"(b[0]), "r"(b[1]));
}

// float4 -> hi (exact bf16 truncation) + lo (bf16 residual); two STS.64.
static __device__ __forceinline__ void cvt_sts(uint32_t hi_a, uint32_t lo_a, float4 x) {
    uint32_t u0 = __float_as_uint(x.x), u1 = __float_as_uint(x.y);
    uint32_t u2 = __float_as_uint(x.z), u3 = __float_as_uint(x.w);
    uint32_t h0, h1;
    asm("prmt.b32 %0, %1, %2, 0x7632;" : "=r"(h0) : "r"(u0), "r"(u1));
    asm("prmt.b32 %0, %1, %2, 0x7632;" : "=r"(h1) : "r"(u2), "r"(u3));
    float f0 = x.x - __uint_as_float(u0 & 0xffff0000u);
    float f1 = x.y - __uint_as_float(u1 & 0xffff0000u);
    float f2 = x.z - __uint_as_float(u2 & 0xffff0000u);
    float f3 = x.w - __uint_as_float(u3 & 0xffff0000u);
    uint32_t l0, l1;
    asm("cvt.rn.bf16x2.f32 %0, %1, %2;" : "=r"(l0) : "f"(f1), "f"(f0));
    asm("cvt.rn.bf16x2.f32 %0, %1, %2;" : "=r"(l1) : "f"(f3), "f"(f2));
    asm volatile("st.shared.v2.b32 [%0], {%1,%2};" :: "r"(hi_a), "r"(h0), "r"(h1) : "memory");
    asm volatile("st.shared.v2.b32 [%0], {%1,%2};" :: "r"(lo_a), "r"(l0), "r"(l1) : "memory");
}

__device__ __forceinline__ float pooled(const float* __restrict__ row, int i, int lvl, int Wl) {
    if (i < 0 || i >= Wl) return 0.0f;
    const int sz = 1 << lvl;
    const float* p = row + (i << lvl);
    float s = 0.0f;
#pragma unroll 8
    for (int k = 0; k < sz; ++k) s += p[k];
    return s * (1.0f / (float)sz);
}

__global__ void __launch_bounds__(NTH, 1)
corr_hmma_kernel(const float* __restrict__ fmap1, const float* __restrict__ fmap2,
                 const float* __restrict__ cents, float* __restrict__ out) {
    extern __shared__ char smem[];
    const uint32_t sb = smem_u32(smem);
    const int t = threadIdx.x, wid = t >> 5, lid = t & 31;
    const int q0 = blockIdx.x * MT, h = blockIdx.y, b = blockIdx.z;
    const int mgrp = wid >> 3;     // 0/1: M half
    const int wN   = wid & 7;      // 0..7: N slice

    // ---- staging tasks ----
    // A (threads 0..255): ch = t>>4, float4 pos = t&15 over 64 queries
    const int cha  = (t & 255) >> 4;
    const int posa = t & 15;
    const float* Ag = fmap1 + ((size_t)b * CC + cha) * HW + (size_t)h * WW + q0 + 4 * posa;
    // B: 1280 float4 tasks (16 ch x 80 pos); thread does u=t, u=t+512, and (t<256) u=1024+t
    const int u0 = t,        ch0 = u0 / 80, ps0 = u0 - 80 * ch0;
    const int u1 = t + 512,  ch1 = u1 / 80, ps1 = u1 - 80 * ch1;
    const int u2 = t + 1024, ch2 = u2 / 80, ps2 = u2 - 80 * ch2;   // t<256 only
    const float* Bg0 = fmap2 + ((size_t)b * CC + ch0) * HW + (size_t)h * WW + 4 * ps0;
    const float* Bg1 = fmap2 + ((size_t)b * CC + ch1) * HW + (size_t)h * WW + 4 * ps1;
    const float* Bg2 = fmap2 + ((size_t)b * CC + ch2) * HW + (size_t)h * WW + 4 * ps2;

    const uint32_t sts_ah = sb + OFF_AH + (uint32_t)(cha * ASTR + 8 * posa);
    const uint32_t sts_al = sb + OFF_AL + (uint32_t)(cha * ASTR + 8 * posa);
    const uint32_t sts_b0h = sb + OFF_BH + (uint32_t)(ch0 * BSTR + 8 * ps0);
    const uint32_t sts_b0l = sb + OFF_BL + (uint32_t)(ch0 * BSTR + 8 * ps0);
    const uint32_t sts_b1h = sb + OFF_BH + (uint32_t)(ch1 * BSTR + 8 * ps1);
    const uint32_t sts_b1l = sb + OFF_BL + (uint32_t)(ch1 * BSTR + 8 * ps1);
    const uint32_t sts_b2h = sb + OFF_BH + (uint32_t)(ch2 * BSTR + 8 * ps2);
    const uint32_t sts_b2l = sb + OFF_BL + (uint32_t)(ch2 * BSTR + 8 * ps2);

    // ---- per-lane ldmatrix offsets ----
    const int r8 = lid & 7, tl = lid >> 3;
    // A: [k][m] rows; +mgrp*64B selects M half (32 cols)
    const uint32_t laneA = (uint32_t)((r8 + 8 * (tl >> 1)) * ASTR + (tl & 1) * 16
                                      + mgrp * 64);
    const uint32_t laneB = (uint32_t)((r8 + 8 * (tl & 1)) * BSTR + (tl >> 1) * 16);
    const uint32_t nbase = (uint32_t)(80 * wN);  // n = 40*wN

    float acc[2][5][4];
#pragma unroll
    for (int i = 0; i < 2; ++i)
#pragma unroll
        for (int j = 0; j < 5; ++j)
#pragma unroll
            for (int k2 = 0; k2 < 4; ++k2) acc[i][j][k2] = 0.0f;

    float4 ra, rb0, rb1, rb2;
    // chunk 0: load + stage into buf0
    if (t < 256) ra = *(const float4*)Ag;
    rb0 = *(const float4*)Bg0;
    rb1 = *(const float4*)Bg1;
    if (t < 256) rb2 = *(const float4*)Bg2;
    if (t < 256) cvt_sts(sts_ah, sts_al, ra);
    cvt_sts(sts_b0h, sts_b0l, rb0);
    cvt_sts(sts_b1h, sts_b1l, rb1);
    if (t < 256) cvt_sts(sts_b2h, sts_b2l, rb2);
    __syncthreads();
    // prefetch chunk 1
    {
        const size_t o = (size_t)KC * HW;
        if (t < 256) ra = *(const float4*)(Ag + o);
        rb0 = *(const float4*)(Bg0 + o);
        rb1 = *(const float4*)(Bg1 + o);
        if (t < 256) rb2 = *(const float4*)(Bg2 + o);
    }

    for (int kc = 0; kc < NCHUNK; ++kc) {
        const uint32_t cur = sb + (uint32_t)((kc & 1) * STAGE_BYTES);
        const uint32_t nxt = (uint32_t)(((kc + 1) & 1) * STAGE_BYTES);

        // ---- fragment loads (each plane once): 9 ldsm/warp ----
        uint32_t ah[2][4], al[2][4], bh[10], bl[10];
        {
            const uint32_t abh = cur + OFF_AH + laneA;
            const uint32_t abl = cur + OFF_AL + laneA;
            ldsm4t(ah[0], abh);       ldsm4t(ah[1], abh + 32u);
            ldsm4t(al[0], abl);       ldsm4t(al[1], abl + 32u);
            const uint32_t bbh = cur + OFF_BH + laneB + nbase;
            const uint32_t bbl = cur + OFF_BL + laneB + nbase;
            ldsm4t(bh + 0, bbh); ldsm4t(bh + 4, bbh + 32u); ldsm2t(bh + 8, bbh + 64u);
            ldsm4t(bl + 0, bbl); ldsm4t(bl + 4, bbl + 32u); ldsm2t(bl + 8, bbl + 64u);
        }

        // ---- stage chunk kc+1 into opposite buffer (drains under MMAs) ----
        if (kc + 1 < NCHUNK) {
            if (t < 256) cvt_sts(sts_ah + nxt, sts_al + nxt, ra);
            cvt_sts(sts_b0h + nxt, sts_b0l + nxt, rb0);
            cvt_sts(sts_b1h + nxt, sts_b1l + nxt, rb1);
            if (t < 256) cvt_sts(sts_b2h + nxt, sts_b2l + nxt, rb2);
            // ---- issue LDGs for chunk kc+2 (covered by MMA phase) ----
            if (kc + 2 < NCHUNK) {
                const size_t o = (size_t)(kc + 2) * KC * HW;
                if (t < 256) ra = *(const float4*)(Ag + o);
                rb0 = *(const float4*)(Bg0 + o);
                rb1 = *(const float4*)(Bg1 + o);
                if (t < 256) rb2 = *(const float4*)(Bg2 + o);
            }
        }

        // ---- 30 MMAs: (Ah,Bh), (Ah,Bl), (Al,Bh) ----
#pragma unroll
        for (int i = 0; i < 2; ++i)
#pragma unroll
            for (int j = 0; j < 5; ++j) {
                mma16816(acc[i][j], ah[i], bh + 2 * j);
                mma16816(acc[i][j], ah[i], bl + 2 * j);
                mma16816(acc[i][j], al[i], bh + 2 * j);
            }

        __syncthreads();  // all frags read + all STS drained before buffer reuse
    }

    // ---- accumulators -> vol (overlays stage smem) ----
    float* vol = (float*)smem;
    {
        const int mr = lid >> 2, nc0 = 2 * (lid & 3);
        const float s = 0.0625f;  // 1/sqrt(256)
#pragma unroll
        for (int i = 0; i < 2; ++i)
#pragma unroll
            for (int j = 0; j < 5; ++j) {
                const int q = mgrp * 32 + 16 * i + mr, v = 40 * wN + 8 * j + nc0;
                *(float2*)&vol[q * VOL_STRIDE + v] =
                    make_float2(acc[i][j][0] * s, acc[i][j][1] * s);
                *(float2*)&vol[(q + 8) * VOL_STRIDE + v] =
                    make_float2(acc[i][j][2] * s, acc[i][j][3] * s);
            }
    }
    __syncthreads();

    // ---- pyramid sampling: 64 q x 36 ch over 512 threads ----
    const int q = t & 63, grp = t >> 6;  // 8 groups
    const float cent = cents[((size_t)b * HH + h) * WW + q0 + q];
    const float* row = vol + q * VOL_STRIDE;
#pragma unroll
    for (int rep = 0; rep < 5; ++rep) {
        const int chn = grp + 8 * rep;
        if (chn >= NCH) break;
        const int lvl = chn / 9, tap = chn - 9 * lvl;
        const int Wl = WW >> lvl;
        const float x  = cent * (1.0f / (float)(1 << lvl)) + (float)(tap - RAD);
        const float x0 = floorf(x);
        const float tt = x - x0;
        const int   i0 = (int)x0;
        const float p0 = pooled(row, i0, lvl, Wl);
        const float p1 = pooled(row, i0 + 1, lvl, Wl);
        out[(((size_t)b * NCH + chn) * HH + h) * WW + q0 + q] = p0 * (1.0f - tt) + p1 * tt;
    }
}

extern "C" void kernel_launch(void* const* d_in, const int* in_sizes, int n_in,
                              void* d_out, int out_size) {
    const float* fmap1 = (const float*)d_in[0];
    const float* fmap2 = (const float*)d_in[1];
    const float* cents = (const float*)d_in[2];
    float* out = (float*)d_out;

    cudaFuncSetAttribute(corr_hmma_kernel,
                         cudaFuncAttributeMaxDynamicSharedMemorySize, SMEM_BYTES);

    dim3 grid(WW / MT, HH, BB);  // (5, 96, 4)
    corr_hmma_kernel<<<grid, NTH, SMEM_BYTES>>>(fmap1, fmap2, cents, out);
}

// round 8
// speedup vs baseline: 1.5443x; 1.5443x over previous
#include <cuda_runtime.h>
#include <cstdint>

// ---------------- problem constants ----------------
#define BB 4
#define CC 256
#define HH 96
#define WW 320
#define HW (HH * WW)          // 30720
#define MT 64                 // queries per CTA
#define KC 32                 // K per chunk = 2 mma k-steps
#define NCHUNK (CC / KC)      // 8
#define NTH 256
#define RAD 4
#define NCH 36
#define VOL_STRIDE 322

// ---------------- smem layout (bytes) ----------------
#define BSTR 656              // B row stride: 328 halves (41*16B, conflict-free)
#define ASTR 176              // A row stride: 88 halves (11*16B)
#define OFF_BH 0
#define OFF_BL (KC * BSTR)            // 20992
#define OFF_AH (2 * KC * BSTR)        // 41984
#define OFF_AL (OFF_AH + KC * ASTR)   // 47616
#define STAGE_BYTES (OFF_AL + KC * ASTR)   // 53248 (x2 stages = 106496)
#define KS_B (16 * BSTR)      // per-kstep offset in B planes (10496)
#define KS_A (16 * ASTR)      // per-kstep offset in A planes (2816)
#define SMEM_BYTES (2 * STAGE_BYTES)       // 106496; vol (82432) overlays

static __device__ __forceinline__ uint32_t smem_u32(const void* p) {
    uint32_t a;
    asm("{ .reg .u64 t; cvta.to.shared.u64 t, %1; cvt.u32.u64 %0, t; }" : "=r"(a) : "l"(p));
    return a;
}

static __device__ __forceinline__ void ldsm4t(uint32_t* r, uint32_t a) {
    asm volatile("ldmatrix.sync.aligned.m8n8.x4.trans.shared.b16 {%0,%1,%2,%3}, [%4];"
                 : "=r"(r[0]), "=r"(r[1]), "=r"(r[2]), "=r"(r[3]) : "r"(a));
}
static __device__ __forceinline__ void ldsm2t(uint32_t* r, uint32_t a) {
    asm volatile("ldmatrix.sync.aligned.m8n8.x2.trans.shared.b16 {%0,%1}, [%2];"
                 : "=r"(r[0]), "=r"(r[1]) : "r"(a));
}
static __device__ __forceinline__ void mma16816(float* d, const uint32_t* a, const uint32_t* b) {
    asm volatile("mma.sync.aligned.m16n8k16.row.col.f32.bf16.bf16.f32 "
                 "{%0,%1,%2,%3}, {%4,%5,%6,%7}, {%8,%9}, {%0,%1,%2,%3};"
                 : "+f"(d[0]), "+f"(d[1]), "+f"(d[2]), "+f"(d[3])
                 : "r"(a[0]), "r"(a[1]), "r"(a[2]), "r"(a[3]), "r"(b[0]), "r"(b[1]));
}

// float4 -> hi (exact bf16 truncation) + lo (bf16 residual); two STS.64.
static __device__ __forceinline__ void cvt_sts(uint32_t hi_a, uint32_t lo_a, float4 x) {
    uint32_t u0 = __float_as_uint(x.x), u1 = __float_as_uint(x.y);
    uint32_t u2 = __float_as_uint(x.z), u3 = __float_as_uint(x.w);
    uint32_t h0, h1;
    asm("prmt.b32 %0, %1, %2, 0x7632;" : "=r"(h0) : "r"(u0), "r"(u1));
    asm("prmt.b32 %0, %1, %2, 0x7632;" : "=r"(h1) : "r"(u2), "r"(u3));
    float f0 = x.x - __uint_as_float(u0 & 0xffff0000u);
    float f1 = x.y - __uint_as_float(u1 & 0xffff0000u);
    float f2 = x.z - __uint_as_float(u2 & 0xffff0000u);
    float f3 = x.w - __uint_as_float(u3 & 0xffff0000u);
    uint32_t l0, l1;
    asm("cvt.rn.bf16x2.f32 %0, %1, %2;" : "=r"(l0) : "f"(f1), "f"(f0));
    asm("cvt.rn.bf16x2.f32 %0, %1, %2;" : "=r"(l1) : "f"(f3), "f"(f2));
    asm volatile("st.shared.v2.b32 [%0], {%1,%2};" :: "r"(hi_a), "r"(h0), "r"(h1) : "memory");
    asm volatile("st.shared.v2.b32 [%0], {%1,%2};" :: "r"(lo_a), "r"(l0), "r"(l1) : "memory");
}

__device__ __forceinline__ float pooled(const float* __restrict__ row, int i, int lvl, int Wl) {
    if (i < 0 || i >= Wl) return 0.0f;
    const int sz = 1 << lvl;
    const float* p = row + (i << lvl);
    float s = 0.0f;
#pragma unroll 8
    for (int k = 0; k < sz; ++k) s += p[k];
    return s * (1.0f / (float)sz);
}

__global__ void __launch_bounds__(NTH, 1)
corr_hmma_kernel(const float* __restrict__ fmap1, const float* __restrict__ fmap2,
                 const float* __restrict__ cents, float* __restrict__ out) {
    extern __shared__ char smem[];
    const uint32_t sb = smem_u32(smem);
    const int t = threadIdx.x, wid = t >> 5, lid = t & 31;
    const int q0 = blockIdx.x * MT, h = blockIdx.y, b = blockIdx.z;

    // ---- load mapping: thread -> (channel-in-kstep, float4 position) ----
    const int ch  = t >> 4;   // 0..15
    const int pos = t & 15;   // 0..15
    const float* Ag = fmap1 + ((size_t)b * CC + ch) * HW + (size_t)h * WW + q0 + 4 * pos;
    const float* Bg = fmap2 + ((size_t)b * CC + ch) * HW + (size_t)h * WW + 4 * pos;

    // ---- per-lane ldmatrix offsets ----
    const int r8 = lid & 7, tl = lid >> 3;
    const uint32_t laneA = (uint32_t)((r8 + 8 * (tl >> 1)) * ASTR + (tl & 1) * 16);
    const uint32_t laneB = (uint32_t)((r8 + 8 * (tl & 1)) * BSTR + (tl >> 1) * 16);
    const uint32_t nbase = (uint32_t)(80 * wid);  // n = 40*wid

    const uint32_t sts_ah = sb + OFF_AH + (uint32_t)(ch * ASTR + 8 * pos);
    const uint32_t sts_al = sb + OFF_AL + (uint32_t)(ch * ASTR + 8 * pos);
    const uint32_t sts_bh = sb + OFF_BH + (uint32_t)(ch * BSTR + 8 * pos);
    const uint32_t sts_bl = sb + OFF_BL + (uint32_t)(ch * BSTR + 8 * pos);

    float acc[4][5][4];
#pragma unroll
    for (int i = 0; i < 4; ++i)
#pragma unroll
        for (int j = 0; j < 5; ++j)
#pragma unroll
            for (int k2 = 0; k2 < 4; ++k2) acc[i][j][k2] = 0.0f;

    float4 ra[2], rb[2][5];
    // chunk 0: load + stage into buf0 (both ksteps)
#pragma unroll
    for (int ks = 0; ks < 2; ++ks) {
        const size_t o = (size_t)(16 * ks) * HW;
        ra[ks] = *(const float4*)(Ag + o);
#pragma unroll
        for (int j = 0; j < 5; ++j) rb[ks][j] = *(const float4*)(Bg + o + 64 * j);
        cvt_sts(sts_ah + (uint32_t)(ks * KS_A), sts_al + (uint32_t)(ks * KS_A), ra[ks]);
#pragma unroll
        for (int j = 0; j < 5; ++j)
            cvt_sts(sts_bh + (uint32_t)(ks * KS_B) + 128u * j,
                    sts_bl + (uint32_t)(ks * KS_B) + 128u * j, rb[ks][j]);
    }
    __syncthreads();
    // prefetch chunk 1
#pragma unroll
    for (int ks = 0; ks < 2; ++ks) {
        const size_t o = (size_t)(KC + 16 * ks) * HW;
        ra[ks] = *(const float4*)(Ag + o);
#pragma unroll
        for (int j = 0; j < 5; ++j) rb[ks][j] = *(const float4*)(Bg + o + 64 * j);
    }

    for (int kc = 0; kc < NCHUNK; ++kc) {
        const uint32_t cur = sb + (uint32_t)((kc & 1) * STAGE_BYTES);
        const uint32_t nxt = (uint32_t)(((kc + 1) & 1) * STAGE_BYTES);

#pragma unroll
        for (int ks = 0; ks < 2; ++ks) {
            const uint32_t ko_a = (uint32_t)(ks * KS_A);
            const uint32_t ko_b = (uint32_t)(ks * KS_B);

            // ---- fragment loads for this kstep (13 ldsm) ----
            uint32_t ah[4][4], al[4][4], bh[10], bl[10];
            {
                const uint32_t abh = cur + OFF_AH + ko_a + laneA;
                const uint32_t abl = cur + OFF_AL + ko_a + laneA;
#pragma unroll
                for (int i = 0; i < 4; ++i) {
                    ldsm4t(ah[i], abh + 32u * i);
                    ldsm4t(al[i], abl + 32u * i);
                }
                const uint32_t bbh = cur + OFF_BH + ko_b + laneB + nbase;
                const uint32_t bbl = cur + OFF_BL + ko_b + laneB + nbase;
                ldsm4t(bh + 0, bbh); ldsm4t(bh + 4, bbh + 32u); ldsm2t(bh + 8, bbh + 64u);
                ldsm4t(bl + 0, bbl); ldsm4t(bl + 4, bbl + 32u); ldsm2t(bl + 8, bbl + 64u);
            }

            // ---- stage this kstep of chunk kc+1 into opposite buffer ----
            if (kc + 1 < NCHUNK) {
                cvt_sts(sts_ah + nxt + ko_a, sts_al + nxt + ko_a, ra[ks]);
#pragma unroll
                for (int j = 0; j < 5; ++j)
                    cvt_sts(sts_bh + nxt + ko_b + 128u * j,
                            sts_bl + nxt + ko_b + 128u * j, rb[ks][j]);
                // ---- LDG this kstep of chunk kc+2 (covered by 120-MMA phase) ----
                if (kc + 2 < NCHUNK) {
                    const size_t o = (size_t)((kc + 2) * KC + 16 * ks) * HW;
                    ra[ks] = *(const float4*)(Ag + o);
#pragma unroll
                    for (int j = 0; j < 5; ++j)
                        rb[ks][j] = *(const float4*)(Bg + o + 64 * j);
                }
            }

            // ---- 60 MMAs: (Ah,Bh), (Ah,Bl), (Al,Bh) ----
#pragma unroll
            for (int i = 0; i < 4; ++i)
#pragma unroll
                for (int j = 0; j < 5; ++j) {
                    mma16816(acc[i][j], ah[i], bh + 2 * j);
                    mma16816(acc[i][j], ah[i], bl + 2 * j);
                    mma16816(acc[i][j], al[i], bh + 2 * j);
                }
        }

        __syncthreads();  // both ksteps' frags read + all STS drained
    }

    // ---- accumulators -> vol (overlays stage smem) ----
    float* vol = (float*)smem;
    {
        const int mr = lid >> 2, nc0 = 2 * (lid & 3);
        const float s = 0.0625f;  // 1/sqrt(256)
#pragma unroll
        for (int i = 0; i < 4; ++i)
#pragma unroll
            for (int j = 0; j < 5; ++j) {
                const int q = 16 * i + mr, v = 40 * wid + 8 * j + nc0;
                *(float2*)&vol[q * VOL_STRIDE + v] =
                    make_float2(acc[i][j][0] * s, acc[i][j][1] * s);
                *(float2*)&vol[(q + 8) * VOL_STRIDE + v] =
                    make_float2(acc[i][j][2] * s, acc[i][j][3] * s);
            }
    }
    __syncthreads();

    // ---- pyramid sampling: 64 q x 36 ch, 9 outputs/thread ----
    const int q = t & 63, grp = t >> 6;
    const float cent = cents[((size_t)b * HH + h) * WW + q0 + q];
    const float* row = vol + q * VOL_STRIDE;
#pragma unroll
    for (int rep = 0; rep < 9; ++rep) {
        const int chn = grp + 4 * rep;
        const int lvl = chn / 9, tap = chn - 9 * lvl;
        const int Wl = WW >> lvl;
        const float x  = cent * (1.0f / (float)(1 << lvl)) + (float)(tap - RAD);
        const float x0 = floorf(x);
        const float tt = x - x0;
        const int   i0 = (int)x0;
        const float p0 = pooled(row, i0, lvl, Wl);
        const float p1 = pooled(row, i0 + 1, lvl, Wl);
        out[(((size_t)b * NCH + chn) * HH + h) * WW + q0 + q] = p0 * (1.0f - tt) + p1 * tt;
    }
}

extern "C" void kernel_launch(void* const* d_in, const int* in_sizes, int n_in,
                              void* d_out, int out_size) {
    const float* fmap1 = (const float*)d_in[0];
    const float* fmap2 = (const float*)d_in[1];
    const float* cents = (const float*)d_in[2];
    float* out = (float*)d_out;

    cudaFuncSetAttribute(corr_hmma_kernel,
                         cudaFuncAttributeMaxDynamicSharedMemorySize, SMEM_BYTES);

    dim3 grid(WW / MT, HH, BB);  // (5, 96, 4)
    corr_hmma_kernel<<<grid, NTH, SMEM_BYTES>>>(fmap1, fmap2, cents, out);
}

// round 9
// speedup vs baseline: 1.5915x; 1.0306x over previous
#include <cuda_runtime.h>
#include <cuda_fp16.h>
#include <cstdint>

// ---------------- problem constants ----------------
#define BB 4
#define CC 256
#define HH 96
#define WW 320
#define HW (HH * WW)          // 30720
#define MT 64                 // queries per CTA
#define KC 32                 // K per chunk = 2 mma k-steps
#define NCHUNK (CC / KC)      // 8
#define NTH 256
#define RAD 4
#define NCH 36

// ---------------- vol layout (floats) ----------------
#define GUARD 80              // zero guard each side (covers all OOB windows)
#define VROW 484              // 80 + 320 + 84; %32==4 -> bank-staggered rows
#define VOL_BYTES (MT * VROW * 4)   // 123904

// ---------------- stage layout (bytes) ----------------
#define BSTR 656              // B row stride: 328 halves (41*16B, conflict-free)
#define ASTR 176              // A row stride: 88 halves (11*16B)
#define OFF_BH 0
#define OFF_AH (KC * BSTR)             // 20992
#define OFF_AL (OFF_AH + KC * ASTR)    // 26624
#define STAGE_BYTES (OFF_AL + KC * ASTR)   // 32256 (x2 stages = 64512)
#define KS_B (16 * BSTR)      // per-kstep offset in B plane (10496)
#define KS_A (16 * ASTR)      // per-kstep offset in A planes (2816)
#define SMEM_BYTES VOL_BYTES  // vol (123904) overlays both stages (64512)

static __device__ __forceinline__ uint32_t smem_u32(const void* p) {
    uint32_t a;
    asm("{ .reg .u64 t; cvta.to.shared.u64 t, %1; cvt.u32.u64 %0, t; }" : "=r"(a) : "l"(p));
    return a;
}

static __device__ __forceinline__ void ldsm4t(uint32_t* r, uint32_t a) {
    asm volatile("ldmatrix.sync.aligned.m8n8.x4.trans.shared.b16 {%0,%1,%2,%3}, [%4];"
                 : "=r"(r[0]), "=r"(r[1]), "=r"(r[2]), "=r"(r[3]) : "r"(a));
}
static __device__ __forceinline__ void ldsm2t(uint32_t* r, uint32_t a) {
    asm volatile("ldmatrix.sync.aligned.m8n8.x2.trans.shared.b16 {%0,%1}, [%2];"
                 : "=r"(r[0]), "=r"(r[1]) : "r"(a));
}
static __device__ __forceinline__ void mma16816(float* d, const uint32_t* a, const uint32_t* b) {
    asm volatile("mma.sync.aligned.m16n8k16.row.col.f32.f16.f16.f32 "
                 "{%0,%1,%2,%3}, {%4,%5,%6,%7}, {%8,%9}, {%0,%1,%2,%3};"
                 : "+f"(d[0]), "+f"(d[1]), "+f"(d[2]), "+f"(d[3])
                 : "r"(a[0]), "r"(a[1]), "r"(a[2]), "r"(a[3]), "r"(b[0]), "r"(b[1]));
}

// B: float4 -> fp16x4 (RN), one STS.64.
static __device__ __forceinline__ void cvt_sts_b(uint32_t addr, float4 x) {
    uint32_t p0, p1;
    asm("cvt.rn.f16x2.f32 %0, %1, %2;" : "=r"(p0) : "f"(x.y), "f"(x.x));
    asm("cvt.rn.f16x2.f32 %0, %1, %2;" : "=r"(p1) : "f"(x.w), "f"(x.z));
    asm volatile("st.shared.v2.b32 [%0], {%1,%2};" :: "r"(addr), "r"(p0), "r"(p1) : "memory");
}

// A: float4 -> hi fp16 (RN) + lo fp16 (residual); two STS.64.
static __device__ __forceinline__ void cvt_sts_a(uint32_t hi_a, uint32_t lo_a, float4 x) {
    uint32_t hp0, hp1;
    asm("cvt.rn.f16x2.f32 %0, %1, %2;" : "=r"(hp0) : "f"(x.y), "f"(x.x));
    asm("cvt.rn.f16x2.f32 %0, %1, %2;" : "=r"(hp1) : "f"(x.w), "f"(x.z));
    __half2 h0 = *(__half2*)&hp0, h1 = *(__half2*)&hp1;
    float r0 = x.x - __low2float(h0),  r1 = x.y - __high2float(h0);
    float r2 = x.z - __low2float(h1),  r3 = x.w - __high2float(h1);
    uint32_t lp0, lp1;
    asm("cvt.rn.f16x2.f32 %0, %1, %2;" : "=r"(lp0) : "f"(r1), "f"(r0));
    asm("cvt.rn.f16x2.f32 %0, %1, %2;" : "=r"(lp1) : "f"(r3), "f"(r2));
    asm volatile("st.shared.v2.b32 [%0], {%1,%2};" :: "r"(hi_a), "r"(hp0), "r"(hp1) : "memory");
    asm volatile("st.shared.v2.b32 [%0], {%1,%2};" :: "r"(lo_a), "r"(lp0), "r"(lp1) : "memory");
}

__global__ void __launch_bounds__(NTH, 1)
corr_hmma_kernel(const float* __restrict__ fmap1, const float* __restrict__ fmap2,
                 const float* __restrict__ cents, float* __restrict__ out) {
    extern __shared__ char smem[];
    const uint32_t sb = smem_u32(smem);
    const int t = threadIdx.x, wid = t >> 5, lid = t & 31;
    const int q0 = blockIdx.x * MT, h = blockIdx.y, b = blockIdx.z;

    // ---- load mapping: thread -> (channel-in-kstep, float4 position) ----
    const int ch  = t >> 4;   // 0..15
    const int pos = t & 15;   // 0..15
    const float* Ag = fmap1 + ((size_t)b * CC + ch) * HW + (size_t)h * WW + q0 + 4 * pos;
    const float* Bg = fmap2 + ((size_t)b * CC + ch) * HW + (size_t)h * WW + 4 * pos;

    // ---- per-lane ldmatrix offsets ----
    const int r8 = lid & 7, tl = lid >> 3;
    const uint32_t laneA = (uint32_t)((r8 + 8 * (tl >> 1)) * ASTR + (tl & 1) * 16);
    const uint32_t laneB = (uint32_t)((r8 + 8 * (tl & 1)) * BSTR + (tl >> 1) * 16);
    const uint32_t nbase = (uint32_t)(80 * wid);  // n = 40*wid

    const uint32_t sts_ah = sb + OFF_AH + (uint32_t)(ch * ASTR + 8 * pos);
    const uint32_t sts_al = sb + OFF_AL + (uint32_t)(ch * ASTR + 8 * pos);
    const uint32_t sts_bh = sb + OFF_BH + (uint32_t)(ch * BSTR + 8 * pos);

    const int ksfirst = (wid >> 2) & 1;  // SMSP pair (w, w+4) staggered

    float acc[4][5][4];
#pragma unroll
    for (int i = 0; i < 4; ++i)
#pragma unroll
        for (int j = 0; j < 5; ++j)
#pragma unroll
            for (int k2 = 0; k2 < 4; ++k2) acc[i][j][k2] = 0.0f;

    float4 ra[2], rb[2][5];
    // chunk 0: load + stage into buf0 (both ksteps)
#pragma unroll
    for (int ks = 0; ks < 2; ++ks) {
        const size_t o = (size_t)(16 * ks) * HW;
        ra[ks] = *(const float4*)(Ag + o);
#pragma unroll
        for (int j = 0; j < 5; ++j) rb[ks][j] = *(const float4*)(Bg + o + 64 * j);
        cvt_sts_a(sts_ah + (uint32_t)(ks * KS_A), sts_al + (uint32_t)(ks * KS_A), ra[ks]);
#pragma unroll
        for (int j = 0; j < 5; ++j)
            cvt_sts_b(sts_bh + (uint32_t)(ks * KS_B) + 128u * j, rb[ks][j]);
    }
    __syncthreads();
    // prefetch chunk 1
#pragma unroll
    for (int ks = 0; ks < 2; ++ks) {
        const size_t o = (size_t)(KC + 16 * ks) * HW;
        ra[ks] = *(const float4*)(Ag + o);
#pragma unroll
        for (int j = 0; j < 5; ++j) rb[ks][j] = *(const float4*)(Bg + o + 64 * j);
    }

    for (int kc = 0; kc < NCHUNK; ++kc) {
        const uint32_t cur = sb + (uint32_t)((kc & 1) * STAGE_BYTES);
        const uint32_t nxt = (uint32_t)(((kc + 1) & 1) * STAGE_BYTES);

#pragma unroll
        for (int ki = 0; ki < 2; ++ki) {
            const int ks = ki ^ ksfirst;
            const uint32_t ko_a = (uint32_t)(ks * KS_A);
            const uint32_t ko_b = (uint32_t)(ks * KS_B);

            // ---- fragment loads for this kstep (11 ldsm) ----
            uint32_t ah[4][4], al[4][4], bh[10];
            {
                const uint32_t abh = cur + OFF_AH + ko_a + laneA;
                const uint32_t abl = cur + OFF_AL + ko_a + laneA;
#pragma unroll
                for (int i = 0; i < 4; ++i) {
                    ldsm4t(ah[i], abh + 32u * i);
                    ldsm4t(al[i], abl + 32u * i);
                }
                const uint32_t bbh = cur + OFF_BH + ko_b + laneB + nbase;
                ldsm4t(bh + 0, bbh); ldsm4t(bh + 4, bbh + 32u); ldsm2t(bh + 8, bbh + 64u);
            }

            // ---- stage this kstep of chunk kc+1 into opposite buffer ----
            if (kc + 1 < NCHUNK) {
                cvt_sts_a(sts_ah + nxt + ko_a, sts_al + nxt + ko_a, ra[ks]);
#pragma unroll
                for (int j = 0; j < 5; ++j)
                    cvt_sts_b(sts_bh + nxt + ko_b + 128u * j, rb[ks][j]);
                // ---- LDG this kstep of chunk kc+2 (covered by MMA phase) ----
                if (kc + 2 < NCHUNK) {
                    const size_t o = (size_t)((kc + 2) * KC + 16 * ks) * HW;
                    ra[ks] = *(const float4*)(Ag + o);
#pragma unroll
                    for (int j = 0; j < 5; ++j)
                        rb[ks][j] = *(const float4*)(Bg + o + 64 * j);
                }
            }

            // ---- 40 MMAs: (Ah + Al) x B ----
#pragma unroll
            for (int i = 0; i < 4; ++i)
#pragma unroll
                for (int j = 0; j < 5; ++j) {
                    mma16816(acc[i][j], ah[i], bh + 2 * j);
                    mma16816(acc[i][j], al[i], bh + 2 * j);
                }
        }

        __syncthreads();  // both ksteps' frags read + all STS drained
    }

    // ---- zero vol guards (stage smem is dead now) ----
    float* vol = (float*)smem;
    {
        const int row = t >> 2, part = t & 3;
        float4 z = make_float4(0.f, 0.f, 0.f, 0.f);
        float4* rp = (float4*)(vol + row * VROW);
#pragma unroll
        for (int i = 0; i < 5; ++i) rp[part + 4 * i] = z;        // left: 20 float4
#pragma unroll
        for (int i = 0; i < 6; ++i) {                             // right: 21 float4
            const int idx = 100 + part + 4 * i;
            if (idx < 121) rp[idx] = z;
        }
    }

    // ---- accumulators -> vol ----
    {
        const int mr = lid >> 2, nc0 = 2 * (lid & 3);
        const float s = 0.0625f;  // 1/sqrt(256)
#pragma unroll
        for (int i = 0; i < 4; ++i)
#pragma unroll
            for (int j = 0; j < 5; ++j) {
                const int q = 16 * i + mr, v = 40 * wid + 8 * j + nc0;
                *(float2*)&vol[q * VROW + GUARD + v] =
                    make_float2(acc[i][j][0] * s, acc[i][j][1] * s);
                *(float2*)&vol[(q + 8) * VROW + GUARD + v] =
                    make_float2(acc[i][j][2] * s, acc[i][j][3] * s);
            }
    }
    __syncthreads();

    // ---- pyramid sampling: thread = (q, level); 10 disjoint windows/thread ----
    {
        const int q = t & 63, lvl = t >> 6;  // lvl uniform per warp pair
        const float cent = cents[((size_t)b * HH + h) * WW + q0 + q];
        const float inv = 1.0f / (float)(1 << lvl);
        const float xl = cent * inv - (float)RAD;
        const float fl = floorf(xl);
        const int i0 = (int)fl;
        const float tt = xl - fl;
        const float* p = vol + q * VROW + GUARD + i0 * (1 << lvl);

        float S[10];
        if (lvl == 0) {
#pragma unroll
            for (int d = 0; d < 10; ++d) S[d] = p[d];
        } else if (lvl == 1) {
#pragma unroll
            for (int d = 0; d < 10; ++d) {
                float2 v = ((const float2*)p)[d];
                S[d] = v.x + v.y;
            }
        } else if (lvl == 2) {
#pragma unroll
            for (int d = 0; d < 10; ++d) {
                float4 v = ((const float4*)p)[d];
                S[d] = (v.x + v.y) + (v.z + v.w);
            }
        } else {
#pragma unroll
            for (int d = 0; d < 10; ++d) {
                float4 v0 = ((const float4*)p)[2 * d];
                float4 v1 = ((const float4*)p)[2 * d + 1];
                S[d] = ((v0.x + v0.y) + (v0.z + v0.w)) + ((v1.x + v1.y) + (v1.z + v1.w));
            }
        }

        float* ob = out + (((size_t)b * NCH + lvl * 9) * HH + h) * WW + q0 + q;
#pragma unroll
        for (int d = 0; d < 9; ++d)
            ob[(size_t)d * HW] = (S[d] * (1.0f - tt) + S[d + 1] * tt) * inv;
    }
}

extern "C" void kernel_launch(void* const* d_in, const int* in_sizes, int n_in,
                              void* d_out, int out_size) {
    const float* fmap1 = (const float*)d_in[0];
    const float* fmap2 = (const float*)d_in[1];
    const float* cents = (const float*)d_in[2];
    float* out = (float*)d_out;

    cudaFuncSetAttribute(corr_hmma_kernel,
                         cudaFuncAttributeMaxDynamicSharedMemorySize, SMEM_BYTES);

    dim3 grid(WW / MT, HH, BB);  // (5, 96, 4)
    corr_hmma_kernel<<<grid, NTH, SMEM_BYTES>>>(fmap1, fmap2, cents, out);
}

// round 10
// speedup vs baseline: 1.8167x; 1.1415x over previous
#include <cuda_runtime.h>
#include <cuda_fp16.h>
#include <cstdint>

// ---------------- problem constants ----------------
#define BB 4
#define CC 256
#define HH 96
#define WW 320
#define HW (HH * WW)          // 30720
#define MT 64                 // queries per CTA
#define KSTEPS 16             // 16 k-phases of 16 channels each
#define NTH 256
#define RAD 4
#define NCH 36

// ---------------- vol layout (floats) ----------------
#define GUARD 80              // zero guard each side (covers all OOB windows)
#define VROW 484              // 80 + 320 + 84; multiple of 4 -> float4 alignment
#define VOL_BYTES (MT * VROW * 4)   // 123904

// ---------------- stage layout (bytes), per kstep stage ----------------
#define BSTR 656              // B row stride: 328 halves (41*16B, conflict-free)
#define ASTR 176              // A row stride: 88 halves (11*16B)
#define OFF_B 0
#define OFF_AH (16 * BSTR)             // 10496
#define OFF_AL (OFF_AH + 16 * ASTR)    // 13312
#define STAGE_BYTES (OFF_AL + 16 * ASTR)   // 16128 (x2 stages = 32256)
#define SMEM_BYTES VOL_BYTES  // vol (123904) overlays both stages (32256)

static __device__ __forceinline__ uint32_t smem_u32(const void* p) {
    uint32_t a;
    asm("{ .reg .u64 t; cvta.to.shared.u64 t, %1; cvt.u32.u64 %0, t; }" : "=r"(a) : "l"(p));
    return a;
}

static __device__ __forceinline__ void ldsm4t(uint32_t* r, uint32_t a) {
    asm volatile("ldmatrix.sync.aligned.m8n8.x4.trans.shared.b16 {%0,%1,%2,%3}, [%4];"
                 : "=r"(r[0]), "=r"(r[1]), "=r"(r[2]), "=r"(r[3]) : "r"(a));
}
static __device__ __forceinline__ void ldsm2t(uint32_t* r, uint32_t a) {
    asm volatile("ldmatrix.sync.aligned.m8n8.x2.trans.shared.b16 {%0,%1}, [%2];"
                 : "=r"(r[0]), "=r"(r[1]) : "r"(a));
}
static __device__ __forceinline__ void mma16816(float* d, const uint32_t* a, const uint32_t* b) {
    asm volatile("mma.sync.aligned.m16n8k16.row.col.f32.f16.f16.f32 "
                 "{%0,%1,%2,%3}, {%4,%5,%6,%7}, {%8,%9}, {%0,%1,%2,%3};"
                 : "+f"(d[0]), "+f"(d[1]), "+f"(d[2]), "+f"(d[3])
                 : "r"(a[0]), "r"(a[1]), "r"(a[2]), "r"(a[3]), "r"(b[0]), "r"(b[1]));
}

// B: float4 -> fp16x4 (RN), one STS.64.
static __device__ __forceinline__ void cvt_sts_b(uint32_t addr, float4 x) {
    uint32_t p0, p1;
    asm("cvt.rn.f16x2.f32 %0, %1, %2;" : "=r"(p0) : "f"(x.y), "f"(x.x));
    asm("cvt.rn.f16x2.f32 %0, %1, %2;" : "=r"(p1) : "f"(x.w), "f"(x.z));
    asm volatile("st.shared.v2.b32 [%0], {%1,%2};" :: "r"(addr), "r"(p0), "r"(p1) : "memory");
}

// A: float4 -> hi fp16 (RN) + lo fp16 (residual); two STS.64.
static __device__ __forceinline__ void cvt_sts_a(uint32_t hi_a, uint32_t lo_a, float4 x) {
    uint32_t hp0, hp1;
    asm("cvt.rn.f16x2.f32 %0, %1, %2;" : "=r"(hp0) : "f"(x.y), "f"(x.x));
    asm("cvt.rn.f16x2.f32 %0, %1, %2;" : "=r"(hp1) : "f"(x.w), "f"(x.z));
    __half2 h0 = *(__half2*)&hp0, h1 = *(__half2*)&hp1;
    float r0 = x.x - __low2float(h0),  r1 = x.y - __high2float(h0);
    float r2 = x.z - __low2float(h1),  r3 = x.w - __high2float(h1);
    uint32_t lp0, lp1;
    asm("cvt.rn.f16x2.f32 %0, %1, %2;" : "=r"(lp0) : "f"(r1), "f"(r0));
    asm("cvt.rn.f16x2.f32 %0, %1, %2;" : "=r"(lp1) : "f"(r3), "f"(r2));
    asm volatile("st.shared.v2.b32 [%0], {%1,%2};" :: "r"(hi_a), "r"(hp0), "r"(hp1) : "memory");
    asm volatile("st.shared.v2.b32 [%0], {%1,%2};" :: "r"(lo_a), "r"(lp0), "r"(lp1) : "memory");
}

__global__ void __launch_bounds__(NTH, 1)
corr_hmma_kernel(const float* __restrict__ fmap1, const float* __restrict__ fmap2,
                 const float* __restrict__ cents, float* __restrict__ out) {
    extern __shared__ char smem[];
    const uint32_t sb = smem_u32(smem);
    const int t = threadIdx.x, wid = t >> 5, lid = t & 31;
    const int q0 = blockIdx.x * MT, h = blockIdx.y, b = blockIdx.z;

    // ---- load mapping: thread -> (channel-in-kstep, float4 position) ----
    const int ch  = t >> 4;   // 0..15
    const int pos = t & 15;   // 0..15
    const float* Ag = fmap1 + ((size_t)b * CC + ch) * HW + (size_t)h * WW + q0 + 4 * pos;
    const float* Bg = fmap2 + ((size_t)b * CC + ch) * HW + (size_t)h * WW + 4 * pos;

    // ---- per-lane ldmatrix offsets ----
    const int r8 = lid & 7, tl = lid >> 3;
    const uint32_t laneA = (uint32_t)((r8 + 8 * (tl >> 1)) * ASTR + (tl & 1) * 16);
    const uint32_t laneB = (uint32_t)((r8 + 8 * (tl & 1)) * BSTR + (tl >> 1) * 16);
    const uint32_t nbase = (uint32_t)(80 * wid);  // n = 40*wid

    const uint32_t sts_ah = sb + OFF_AH + (uint32_t)(ch * ASTR + 8 * pos);
    const uint32_t sts_al = sb + OFF_AL + (uint32_t)(ch * ASTR + 8 * pos);
    const uint32_t sts_b  = sb + OFF_B  + (uint32_t)(ch * BSTR + 8 * pos);

    float acc[4][5][4];
#pragma unroll
    for (int i = 0; i < 4; ++i)
#pragma unroll
        for (int j = 0; j < 5; ++j)
#pragma unroll
            for (int k2 = 0; k2 < 4; ++k2) acc[i][j][k2] = 0.0f;

    // ---- prologue: kstep 0 -> stage 0; kstep 1 -> registers ----
    float4 ra, rb[5];
    ra = *(const float4*)Ag;
#pragma unroll
    for (int j = 0; j < 5; ++j) rb[j] = *(const float4*)(Bg + 64 * j);
    cvt_sts_a(sts_ah, sts_al, ra);
#pragma unroll
    for (int j = 0; j < 5; ++j) cvt_sts_b(sts_b + 128u * j, rb[j]);
    {
        const size_t o = (size_t)16 * HW;
        ra = *(const float4*)(Ag + o);
#pragma unroll
        for (int j = 0; j < 5; ++j) rb[j] = *(const float4*)(Bg + o + 64 * j);
    }
    __syncthreads();

    // ---- mainloop: one kstep per phase, 2-stage ring, 1 barrier/phase ----
#pragma unroll 2
    for (int p = 0; p < KSTEPS; ++p) {
        const uint32_t cur = sb + (uint32_t)((p & 1) * STAGE_BYTES);
        const uint32_t nxtoff = (uint32_t)(((p + 1) & 1) * STAGE_BYTES);

        // ---- fragment loads (11 ldsm) ----
        uint32_t ah[4][4], al[4][4], bh[10];
        {
            const uint32_t abh = cur + OFF_AH + laneA;
            const uint32_t abl = cur + OFF_AL + laneA;
#pragma unroll
            for (int i = 0; i < 4; ++i) {
                ldsm4t(ah[i], abh + 32u * i);
                ldsm4t(al[i], abl + 32u * i);
            }
            const uint32_t bbh = cur + OFF_B + laneB + nbase;
            ldsm4t(bh + 0, bbh); ldsm4t(bh + 4, bbh + 32u); ldsm2t(bh + 8, bbh + 64u);
        }

        // ---- stage kstep p+1 from registers; refill registers with kstep p+2 ----
        if (p + 1 < KSTEPS) {
            cvt_sts_a(sts_ah + nxtoff, sts_al + nxtoff, ra);
#pragma unroll
            for (int j = 0; j < 5; ++j) cvt_sts_b(sts_b + nxtoff + 128u * j, rb[j]);
            if (p + 2 < KSTEPS) {
                const size_t o = (size_t)((p + 2) * 16) * HW;
                ra = *(const float4*)(Ag + o);
#pragma unroll
                for (int j = 0; j < 5; ++j) rb[j] = *(const float4*)(Bg + o + 64 * j);
            }
        }

        // ---- 40 MMAs: (Ah + Al) x B ----
#pragma unroll
        for (int i = 0; i < 4; ++i)
#pragma unroll
            for (int j = 0; j < 5; ++j) {
                mma16816(acc[i][j], ah[i], bh + 2 * j);
                mma16816(acc[i][j], al[i], bh + 2 * j);
            }

        __syncthreads();  // frags read + STS drained before buffer reuse
    }

    // ---- zero vol guards (stage smem is dead now) ----
    float* vol = (float*)smem;
    {
        const int row = t >> 2, part = t & 3;
        float4 z = make_float4(0.f, 0.f, 0.f, 0.f);
        float4* rp = (float4*)(vol + row * VROW);
#pragma unroll
        for (int i = 0; i < 5; ++i) rp[part + 4 * i] = z;        // left: 20 float4
#pragma unroll
        for (int i = 0; i < 6; ++i) {                             // right: 21 float4
            const int idx = 100 + part + 4 * i;
            if (idx < 121) rp[idx] = z;
        }
    }

    // ---- accumulators -> vol ----
    {
        const int mr = lid >> 2, nc0 = 2 * (lid & 3);
        const float s = 0.0625f;  // 1/sqrt(256)
#pragma unroll
        for (int i = 0; i < 4; ++i)
#pragma unroll
            for (int j = 0; j < 5; ++j) {
                const int q = 16 * i + mr, v = 40 * wid + 8 * j + nc0;
                *(float2*)&vol[q * VROW + GUARD + v] =
                    make_float2(acc[i][j][0] * s, acc[i][j][1] * s);
                *(float2*)&vol[(q + 8) * VROW + GUARD + v] =
                    make_float2(acc[i][j][2] * s, acc[i][j][3] * s);
            }
    }
    __syncthreads();

    // ---- pyramid sampling: thread = (q, level); 10 disjoint windows/thread ----
    {
        const int q = t & 63, lvl = t >> 6;  // lvl uniform per warp pair
        const float cent = cents[((size_t)b * HH + h) * WW + q0 + q];
        const float inv = 1.0f / (float)(1 << lvl);
        const float xl = cent * inv - (float)RAD;
        const float fl = floorf(xl);
        const int i0 = (int)fl;
        const float tt = xl - fl;
        const float* p = vol + q * VROW + GUARD + i0 * (1 << lvl);

        float S[10];
        if (lvl == 0) {
#pragma unroll
            for (int d = 0; d < 10; ++d) S[d] = p[d];
        } else if (lvl == 1) {
#pragma unroll
            for (int d = 0; d < 10; ++d) {
                float2 v = ((const float2*)p)[d];
                S[d] = v.x + v.y;
            }
        } else if (lvl == 2) {
#pragma unroll
            for (int d = 0; d < 10; ++d) {
                float4 v = ((const float4*)p)[d];
                S[d] = (v.x + v.y) + (v.z + v.w);
            }
        } else {
#pragma unroll
            for (int d = 0; d < 10; ++d) {
                float4 v0 = ((const float4*)p)[2 * d];
                float4 v1 = ((const float4*)p)[2 * d + 1];
                S[d] = ((v0.x + v0.y) + (v0.z + v0.w)) + ((v1.x + v1.y) + (v1.z + v1.w));
            }
        }

        float* ob = out + (((size_t)b * NCH + lvl * 9) * HH + h) * WW + q0 + q;
#pragma unroll
        for (int d = 0; d < 9; ++d)
            ob[(size_t)d * HW] = (S[d] * (1.0f - tt) + S[d + 1] * tt) * inv;
    }
}

extern "C" void kernel_launch(void* const* d_in, const int* in_sizes, int n_in,
                              void* d_out, int out_size) {
    const float* fmap1 = (const float*)d_in[0];
    const float* fmap2 = (const float*)d_in[1];
    const float* cents = (const float*)d_in[2];
    float* out = (float*)d_out;

    cudaFuncSetAttribute(corr_hmma_kernel,
                         cudaFuncAttributeMaxDynamicSharedMemorySize, SMEM_BYTES);

    dim3 grid(WW / MT, HH, BB);  // (5, 96, 4)
    corr_hmma_kernel<<<grid, NTH, SMEM_BYTES>>>(fmap1, fmap2, cents, out);
}

// round 12
// speedup vs baseline: 2.2570x; 1.2424x over previous
#include <cuda_runtime.h>
#include <cuda_fp16.h>
#include <cstdint>

// ---------------- problem constants ----------------
#define BB 4
#define CC 256
#define HH 96
#define WW 320
#define HW (HH * WW)          // 30720
#define MT 64                 // queries per CTA
#define NCHUNK 8              // 8 chunks of 32 channels (2 ksteps)
#define NTH 256
#define RAD 4
#define NCH 36

// ---------------- vol layout (floats) ----------------
#define GUARD 80              // zero guard each side (covers all OOB windows)
#define VROW 484              // 80 + 320 + 84; multiple of 4 -> float4 alignment
#define VOL_BYTES (MT * VROW * 4)   // 123904

// ---------------- stage layout (bytes), per 2-kstep stage ----------------
#define BSTR 656              // B row stride: 328 halves (41*16B, conflict-free)
#define ASTR 176              // A row stride: 88 halves (11*16B)
#define OFF_B 0
#define OFF_AH (32 * BSTR)             // 20992
#define OFF_AL (OFF_AH + 32 * ASTR)    // 26624
#define STAGE_BYTES (OFF_AL + 32 * ASTR)   // 32256 (x2 stages = 64512)
#define KS_B (16 * BSTR)      // per-kstep offset in B plane (10496)
#define KS_A (16 * ASTR)      // per-kstep offset in A planes (2816)
#define SMEM_BYTES VOL_BYTES  // vol (123904) overlays both stages (64512)

static __device__ __forceinline__ uint32_t smem_u32(const void* p) {
    uint32_t a;
    asm("{ .reg .u64 t; cvta.to.shared.u64 t, %1; cvt.u32.u64 %0, t; }" : "=r"(a) : "l"(p));
    return a;
}

static __device__ __forceinline__ void ldsm4t(uint32_t* r, uint32_t a) {
    asm volatile("ldmatrix.sync.aligned.m8n8.x4.trans.shared.b16 {%0,%1,%2,%3}, [%4];"
                 : "=r"(r[0]), "=r"(r[1]), "=r"(r[2]), "=r"(r[3]) : "r"(a));
}
static __device__ __forceinline__ void ldsm2t(uint32_t* r, uint32_t a) {
    asm volatile("ldmatrix.sync.aligned.m8n8.x2.trans.shared.b16 {%0,%1}, [%2];"
                 : "=r"(r[0]), "=r"(r[1]) : "r"(a));
}
static __device__ __forceinline__ void mma16816(float* d, const uint32_t* a, const uint32_t* b) {
    asm volatile("mma.sync.aligned.m16n8k16.row.col.f32.f16.f16.f32 "
                 "{%0,%1,%2,%3}, {%4,%5,%6,%7}, {%8,%9}, {%0,%1,%2,%3};"
                 : "+f"(d[0]), "+f"(d[1]), "+f"(d[2]), "+f"(d[3])
                 : "r"(a[0]), "r"(a[1]), "r"(a[2]), "r"(a[3]), "r"(b[0]), "r"(b[1]));
}

// B: float4 -> fp16x4 (RN), one STS.64.
static __device__ __forceinline__ void cvt_sts_b(uint32_t addr, float4 x) {
    uint32_t p0, p1;
    asm("cvt.rn.f16x2.f32 %0, %1, %2;" : "=r"(p0) : "f"(x.y), "f"(x.x));
    asm("cvt.rn.f16x2.f32 %0, %1, %2;" : "=r"(p1) : "f"(x.w), "f"(x.z));
    asm volatile("st.shared.v2.b32 [%0], {%1,%2};" :: "r"(addr), "r"(p0), "r"(p1) : "memory");
}

// A: float4 -> hi fp16 (RN) + lo fp16 (residual); two STS.64.
static __device__ __forceinline__ void cvt_sts_a(uint32_t hi_a, uint32_t lo_a, float4 x) {
    uint32_t hp0, hp1;
    asm("cvt.rn.f16x2.f32 %0, %1, %2;" : "=r"(hp0) : "f"(x.y), "f"(x.x));
    asm("cvt.rn.f16x2.f32 %0, %1, %2;" : "=r"(hp1) : "f"(x.w), "f"(x.z));
    __half2 h0 = *(__half2*)&hp0, h1 = *(__half2*)&hp1;
    float r0 = x.x - __low2float(h0),  r1 = x.y - __high2float(h0);
    float r2 = x.z - __low2float(h1),  r3 = x.w - __high2float(h1);
    uint32_t lp0, lp1;
    asm("cvt.rn.f16x2.f32 %0, %1, %2;" : "=r"(lp0) : "f"(r1), "f"(r0));
    asm("cvt.rn.f16x2.f32 %0, %1, %2;" : "=r"(lp1) : "f"(r3), "f"(r2));
    asm volatile("st.shared.v2.b32 [%0], {%1,%2};" :: "r"(hi_a), "r"(hp0), "r"(hp1) : "memory");
    asm volatile("st.shared.v2.b32 [%0], {%1,%2};" :: "r"(lo_a), "r"(lp0), "r"(lp1) : "memory");
}

__global__ void __launch_bounds__(NTH, 1)
corr_hmma_kernel(const float* __restrict__ fmap1, const float* __restrict__ fmap2,
                 const float* __restrict__ cents, float* __restrict__ out) {
    extern __shared__ char smem[];
    const uint32_t sb = smem_u32(smem);
    const int t = threadIdx.x, wid = t >> 5, lid = t & 31;
    const int q0 = blockIdx.x * MT, h = blockIdx.y, b = blockIdx.z;

    // ---- load mapping: thread -> (channel-in-kstep, float4 position) ----
    const int ch  = t >> 4;   // 0..15
    const int pos = t & 15;   // 0..15
    const float* Ag = fmap1 + ((size_t)b * CC + ch) * HW + (size_t)h * WW + q0 + 4 * pos;
    const float* Bg = fmap2 + ((size_t)b * CC + ch) * HW + (size_t)h * WW + 4 * pos;

    // ---- per-lane ldmatrix offsets ----
    const int r8 = lid & 7, tl = lid >> 3;
    const uint32_t laneA = (uint32_t)((r8 + 8 * (tl >> 1)) * ASTR + (tl & 1) * 16);
    const uint32_t laneB = (uint32_t)((r8 + 8 * (tl & 1)) * BSTR + (tl >> 1) * 16);
    const uint32_t nbase = (uint32_t)(80 * wid);  // n = 40*wid

    const uint32_t sts_ah = sb + OFF_AH + (uint32_t)(ch * ASTR + 8 * pos);
    const uint32_t sts_al = sb + OFF_AL + (uint32_t)(ch * ASTR + 8 * pos);
    const uint32_t sts_b  = sb + OFF_B  + (uint32_t)(ch * BSTR + 8 * pos);

    float acc[4][5][4];
#pragma unroll
    for (int i = 0; i < 4; ++i)
#pragma unroll
        for (int j = 0; j < 5; ++j)
#pragma unroll
            for (int k2 = 0; k2 < 4; ++k2) acc[i][j][k2] = 0.0f;

    // ---- prologue: chunk 0 (both ksteps) -> stage 0; chunk 1 -> registers ----
    float4 ra[2], rb[2][5];
#pragma unroll
    for (int ks = 0; ks < 2; ++ks) {
        const size_t o = (size_t)(16 * ks) * HW;
        ra[ks] = *(const float4*)(Ag + o);
#pragma unroll
        for (int j = 0; j < 5; ++j) rb[ks][j] = *(const float4*)(Bg + o + 64 * j);
        cvt_sts_a(sts_ah + (uint32_t)(ks * KS_A), sts_al + (uint32_t)(ks * KS_A), ra[ks]);
#pragma unroll
        for (int j = 0; j < 5; ++j)
            cvt_sts_b(sts_b + (uint32_t)(ks * KS_B) + 128u * j, rb[ks][j]);
    }
#pragma unroll
    for (int ks = 0; ks < 2; ++ks) {
        const size_t o = (size_t)(32 + 16 * ks) * HW;
        ra[ks] = *(const float4*)(Ag + o);
#pragma unroll
        for (int j = 0; j < 5; ++j) rb[ks][j] = *(const float4*)(Bg + o + 64 * j);
    }
    __syncthreads();

    // ---- mainloop: 2 ksteps per phase, one barrier per 80 MMAs ----
    for (int c = 0; c < NCHUNK; ++c) {
        const uint32_t cur = sb + (uint32_t)((c & 1) * STAGE_BYTES);
        const uint32_t nxtoff = (uint32_t)(((c + 1) & 1) * STAGE_BYTES);

        // ---- frags kstep 0 (exposed chain — once per phase) ----
        uint32_t ah0[4][4], al0[4][4], bh0[10];
        {
            const uint32_t abh = cur + OFF_AH + laneA;
            const uint32_t abl = cur + OFF_AL + laneA;
#pragma unroll
            for (int i = 0; i < 4; ++i) {
                ldsm4t(ah0[i], abh + 32u * i);
                ldsm4t(al0[i], abl + 32u * i);
            }
            const uint32_t bb = cur + OFF_B + laneB + nbase;
            ldsm4t(bh0 + 0, bb); ldsm4t(bh0 + 4, bb + 32u); ldsm2t(bh0 + 8, bb + 64u);
        }

        // ---- MMA kstep 0 (40) ----
#pragma unroll
        for (int i = 0; i < 4; ++i)
#pragma unroll
            for (int j = 0; j < 5; ++j) {
                mma16816(acc[i][j], ah0[i], bh0 + 2 * j);
                mma16816(acc[i][j], al0[i], bh0 + 2 * j);
            }

        // ---- frags kstep 1 (issues while kstep-0 MMAs drain) ----
        uint32_t ah1[4][4], al1[4][4], bh1[10];
        {
            const uint32_t abh = cur + OFF_AH + (uint32_t)KS_A + laneA;
            const uint32_t abl = cur + OFF_AL + (uint32_t)KS_A + laneA;
#pragma unroll
            for (int i = 0; i < 4; ++i) {
                ldsm4t(ah1[i], abh + 32u * i);
                ldsm4t(al1[i], abl + 32u * i);
            }
            const uint32_t bb = cur + OFF_B + (uint32_t)KS_B + laneB + nbase;
            ldsm4t(bh1 + 0, bb); ldsm4t(bh1 + 4, bb + 32u); ldsm2t(bh1 + 8, bb + 64u);
        }

        // ---- stage chunk c+1 (both ksteps); refill regs with chunk c+2 ----
        if (c + 1 < NCHUNK) {
#pragma unroll
            for (int ks = 0; ks < 2; ++ks) {
                const uint32_t ko_a = nxtoff + (uint32_t)(ks * KS_A);
                const uint32_t ko_b = nxtoff + (uint32_t)(ks * KS_B);
                cvt_sts_a(sts_ah + ko_a, sts_al + ko_a, ra[ks]);
#pragma unroll
                for (int j = 0; j < 5; ++j)
                    cvt_sts_b(sts_b + ko_b + 128u * j, rb[ks][j]);
            }
            if (c + 2 < NCHUNK) {
#pragma unroll
                for (int ks = 0; ks < 2; ++ks) {
                    const size_t o = (size_t)((c + 2) * 32 + 16 * ks) * HW;
                    ra[ks] = *(const float4*)(Ag + o);
#pragma unroll
                    for (int j = 0; j < 5; ++j)
                        rb[ks][j] = *(const float4*)(Bg + o + 64 * j);
                }
            }
        }

        // ---- MMA kstep 1 (40) ----
#pragma unroll
        for (int i = 0; i < 4; ++i)
#pragma unroll
            for (int j = 0; j < 5; ++j) {
                mma16816(acc[i][j], ah1[i], bh1 + 2 * j);
                mma16816(acc[i][j], al1[i], bh1 + 2 * j);
            }

        __syncthreads();  // frags read + STS drained before buffer reuse
    }

    // ---- zero vol guards (stage smem is dead now) ----
    float* vol = (float*)smem;
    {
        const int row = t >> 2, part = t & 3;
        float4 z = make_float4(0.f, 0.f, 0.f, 0.f);
        float4* rp = (float4*)(vol + row * VROW);
#pragma unroll
        for (int i = 0; i < 5; ++i) rp[part + 4 * i] = z;        // left: 20 float4
#pragma unroll
        for (int i = 0; i < 6; ++i) {                             // right: 21 float4
            const int idx = 100 + part + 4 * i;
            if (idx < 121) rp[idx] = z;
        }
    }

    // ---- accumulators -> vol ----
    {
        const int mr = lid >> 2, nc0 = 2 * (lid & 3);
        const float s = 0.0625f;  // 1/sqrt(256)
#pragma unroll
        for (int i = 0; i < 4; ++i)
#pragma unroll
            for (int j = 0; j < 5; ++j) {
                const int q = 16 * i + mr, v = 40 * wid + 8 * j + nc0;
                *(float2*)&vol[q * VROW + GUARD + v] =
                    make_float2(acc[i][j][0] * s, acc[i][j][1] * s);
                *(float2*)&vol[(q + 8) * VROW + GUARD + v] =
                    make_float2(acc[i][j][2] * s, acc[i][j][3] * s);
            }
    }
    __syncthreads();

    // ---- pyramid sampling: thread = (q, level); 10 disjoint windows/thread ----
    {
        const int q = t & 63, lvl = t >> 6;  // lvl uniform per warp pair
        const float cent = cents[((size_t)b * HH + h) * WW + q0 + q];
        const float inv = 1.0f / (float)(1 << lvl);
        const float xl = cent * inv - (float)RAD;
        const float fl = floorf(xl);
        const int i0 = (int)fl;
        const float tt = xl - fl;
        const float* p = vol + q * VROW + GUARD + i0 * (1 << lvl);

        float S[10];
        if (lvl == 0) {
#pragma unroll
            for (int d = 0; d < 10; ++d) S[d] = p[d];
        } else if (lvl == 1) {
#pragma unroll
            for (int d = 0; d < 10; ++d) {
                float2 v = ((const float2*)p)[d];
                S[d] = v.x + v.y;
            }
        } else if (lvl == 2) {
#pragma unroll
            for (int d = 0; d < 10; ++d) {
                float4 v = ((const float4*)p)[d];
                S[d] = (v.x + v.y) + (v.z + v.w);
            }
        } else {
#pragma unroll
            for (int d = 0; d < 10; ++d) {
                float4 v0 = ((const float4*)p)[2 * d];
                float4 v1 = ((const float4*)p)[2 * d + 1];
                S[d] = ((v0.x + v0.y) + (v0.z + v0.w)) + ((v1.x + v1.y) + (v1.z + v1.w));
            }
        }

        float* ob = out + (((size_t)b * NCH + lvl * 9) * HH + h) * WW + q0 + q;
#pragma unroll
        for (int d = 0; d < 9; ++d)
            ob[(size_t)d * HW] = (S[d] * (1.0f - tt) + S[d + 1] * tt) * inv;
    }
}

extern "C" void kernel_launch(void* const* d_in, const int* in_sizes, int n_in,
                              void* d_out, int out_size) {
    const float* fmap1 = (const float*)d_in[0];
    const float* fmap2 = (const float*)d_in[1];
    const float* cents = (const float*)d_in[2];
    float* out = (float*)d_out;

    cudaFuncSetAttribute(corr_hmma_kernel,
                         cudaFuncAttributeMaxDynamicSharedMemorySize, SMEM_BYTES);

    dim3 grid(WW / MT, HH, BB);  // (5, 96, 4)
    corr_hmma_kernel<<<grid, NTH, SMEM_BYTES>>>(fmap1, fmap2, cents, out);
}